// round 7
// baseline (speedup 1.0000x reference)
#include <cuda_runtime.h>

// out[i] = x[i] - max(ceil(x[i]), 1.0f)
// Flat streaming kernel: FOUR float4 per thread, front-batched independent
// loads at quarter-stride offsets. 32-bit indexing, streaming cache hints.
// n = 2^27 -> n4 = 2^25, divisible by 4: main path is guard-free in practice.

__device__ __forceinline__ float f(float v) {
    return v - fmaxf(ceilf(v), 1.0f);
}

__device__ __forceinline__ float4 f4(float4 v) {
    float4 r;
    r.x = f(v.x); r.y = f(v.y); r.z = f(v.z); r.w = f(v.w);
    return r;
}

__global__ void __launch_bounds__(256)
recur_kernel_flat4(const float4* __restrict__ x, float4* __restrict__ out,
                   unsigned q, unsigned n4) {
    unsigned i = blockIdx.x * 256u + threadIdx.x;
    if (i >= q) return;
    unsigned i1 = i + q, i2 = i + 2u * q, i3 = i + 3u * q;

    if (i3 < n4) {
        // Fast path: 4 independent 128-bit loads in flight before any store.
        float4 v0 = __ldcs(&x[i]);
        float4 v1 = __ldcs(&x[i1]);
        float4 v2 = __ldcs(&x[i2]);
        float4 v3 = __ldcs(&x[i3]);
        __stcs(&out[i],  f4(v0));
        __stcs(&out[i1], f4(v1));
        __stcs(&out[i2], f4(v2));
        __stcs(&out[i3], f4(v3));
    } else {
        __stcs(&out[i], f4(__ldcs(&x[i])));
        if (i1 < n4) __stcs(&out[i1], f4(__ldcs(&x[i1])));
        if (i2 < n4) __stcs(&out[i2], f4(__ldcs(&x[i2])));
    }
}

__global__ void recur_kernel_tail(const float* __restrict__ x, float* __restrict__ out,
                                  long start, long n) {
    long i = start + (long)blockIdx.x * blockDim.x + threadIdx.x;
    if (i < n) out[i] = f(x[i]);
}

extern "C" void kernel_launch(void* const* d_in, const int* in_sizes, int n_in,
                              void* d_out, int out_size) {
    const float* x = (const float*)d_in[0];
    float* out = (float*)d_out;
    long n = (long)in_sizes[0];

    long n4 = n / 4;
    if (n4 > 0) {
        unsigned un4 = (unsigned)n4;
        unsigned q = (un4 + 3u) / 4u;   // slots: [0,q), [q,2q), [2q,3q), [3q,n4)
        unsigned blocks = (q + 255u) / 256u;
        recur_kernel_flat4<<<blocks, 256>>>((const float4*)x, (float4*)out, q, un4);
    }
    long rem_start = n4 * 4;
    long rem = n - rem_start;
    if (rem > 0) {
        int threads = 256;
        int blocks = (int)((rem + threads - 1) / threads);
        recur_kernel_tail<<<blocks, threads>>>(x, out, rem_start, n);
    }
}

// round 9
// speedup vs baseline: 1.0127x; 1.0127x over previous
#include <cuda_runtime.h>

// out[i] = x[i] - max(ceil(x[i]), 1.0f)
// Flat streaming kernel: two float4 per thread, front-batched, CTA-LOCAL
// layout: both accesses of a thread land in the same contiguous 8KB window
// owned by its CTA (better DRAM row-buffer locality than far-strided slots).

__device__ __forceinline__ float f(float v) {
    return v - fmaxf(ceilf(v), 1.0f);
}

__device__ __forceinline__ float4 f4(float4 v) {
    float4 r;
    r.x = f(v.x); r.y = f(v.y); r.z = f(v.z); r.w = f(v.w);
    return r;
}

__global__ void __launch_bounds__(256)
recur_kernel_flat2b(const float4* __restrict__ x, float4* __restrict__ out, unsigned n4) {
    // Each CTA owns a contiguous window of 512 float4 (8KB).
    unsigned base = blockIdx.x * 512u;
    unsigned i0 = base + threadIdx.x;        // first 4KB half of window
    unsigned i1 = i0 + 256u;                 // second 4KB half of window

    if (i1 < n4) {
        // Fast path: both accesses in-bounds (always true for n = 2^27).
        float4 v0 = __ldcs(&x[i0]);
        float4 v1 = __ldcs(&x[i1]);
        __stcs(&out[i0], f4(v0));
        __stcs(&out[i1], f4(v1));
    } else {
        if (i0 < n4) __stcs(&out[i0], f4(__ldcs(&x[i0])));
    }
}

__global__ void recur_kernel_tail(const float* __restrict__ x, float* __restrict__ out,
                                  long start, long n) {
    long i = start + (long)blockIdx.x * blockDim.x + threadIdx.x;
    if (i < n) out[i] = f(x[i]);
}

extern "C" void kernel_launch(void* const* d_in, const int* in_sizes, int n_in,
                              void* d_out, int out_size) {
    const float* x = (const float*)d_in[0];
    float* out = (float*)d_out;
    long n = (long)in_sizes[0];

    long n4 = n / 4;
    if (n4 > 0) {
        unsigned un4 = (unsigned)n4;
        unsigned blocks = (un4 + 511u) / 512u;   // 512 float4 per CTA
        recur_kernel_flat2b<<<blocks, 256>>>((const float4*)x, (float4*)out, un4);
    }
    long rem_start = n4 * 4;
    long rem = n - rem_start;
    if (rem > 0) {
        int threads = 256;
        int blocks = (int)((rem + threads - 1) / threads);
        recur_kernel_tail<<<blocks, threads>>>(x, out, rem_start, n);
    }
}